// round 4
// baseline (speedup 1.0000x reference)
#include <cuda_runtime.h>
#include <cstdint>

#define NB 128   // batch
#define NC 16    // c rows
#define NF 128   // f cols
#define ND 512   // feature dim
#define NEG_INF __int_as_float(0xff800000)

// Scratch (no cudaMalloc allowed): xn stored transposed per m: [m][d][c]
__device__ float g_xnT[NB * ND * NC];     // 4 MB
__device__ float g_fnorm[NB * NF];        // 64 KB

// ---------------------------------------------------------------------------
// Kernel 1: normalize c_feats (store d-major transposed) + f row norms
// ---------------------------------------------------------------------------
__global__ void __launch_bounds__(128) prep_kernel(
    const float* __restrict__ c_feats, const float* __restrict__ f_feats)
{
    const int b   = blockIdx.x;
    const int tid = threadIdx.x;
    const bool is_c = (b < NB * NC);
    const float* row = is_c ? (c_feats + (size_t)b * ND)
                            : (f_feats + (size_t)(b - NB * NC) * ND);
    float4 x = ((const float4*)row)[tid];   // 128 threads * 4 = 512
    float ss = x.x * x.x + x.y * x.y + x.z * x.z + x.w * x.w;
    #pragma unroll
    for (int o = 16; o; o >>= 1) ss += __shfl_xor_sync(0xffffffffu, ss, o);
    __shared__ float wr[4];
    if ((tid & 31) == 0) wr[tid >> 5] = ss;
    __syncthreads();
    float nrm = sqrtf(wr[0] + wr[1] + wr[2] + wr[3]);

    if (is_c) {
        int m = b >> 4, c = b & 15;
        float* dst = g_xnT + (size_t)m * (ND * NC) + c;
        int d0 = tid * 4;
        dst[(size_t)(d0 + 0) * NC] = x.x / nrm;
        dst[(size_t)(d0 + 1) * NC] = x.y / nrm;
        dst[(size_t)(d0 + 2) * NC] = x.z / nrm;
        dst[(size_t)(d0 + 3) * NC] = x.w / nrm;
    } else {
        if (tid == 0) g_fnorm[b - NB * NC] = nrm;
    }
}

// ---------------------------------------------------------------------------
// Kernel 2: per-pair GEMM + DTW + backtrack + mask store.
// One CTA per (m,n) pair, 128 threads = one per f column.
// f column values live in REGISTERS (direct LDG, no smem staging).
// x tile [512 d][16 c] in SMEM, read via broadcast LDS.128.
//
// SMEM layout (floats), 8192 total (32 KB static):
//   GEMM phase : xs  [0, 8192)
//   DP phase   : Dm  [0, 2193)  (17 rows x 129)
//                wrs [2200, 2204), wrm [2204, 2208)
//                mask[4096, 6144)  (16 x 128)
// ---------------------------------------------------------------------------
__device__ __forceinline__ void fma2(unsigned long long& d,
                                     unsigned long long a,
                                     unsigned long long b) {
    asm("fma.rn.f32x2 %0, %1, %2, %0;" : "+l"(d) : "l"(a), "l"(b));
}

__global__ void __launch_bounds__(128, 6) dtw_kernel(
    const float* __restrict__ f_feats, float* __restrict__ out)
{
    __shared__ float smem[8192];
    float* xs   = smem;
    float* Dm   = smem;            // reuse after GEMM
    float* wrs  = smem + 2200;
    float* wrm  = smem + 2204;
    float* mask = smem + 4096;     // reuse after GEMM

    const int pair = blockIdx.x;
    const int m = pair & 127;      // m fastest -> concurrent CTAs share f[n]
    const int n = pair >> 7;
    const int tid  = threadIdx.x;
    const int lane = tid & 31;
    const int wid  = tid >> 5;

    // ---- load normalized X tile (contiguous: g_xnT already [d][c]) ----
    {
        const float4* xg  = (const float4*)(g_xnT + (size_t)m * (ND * NC));
        float4*       xd4 = (float4*)xs;
        #pragma unroll
        for (int w = 0; w < 16; w++) xd4[tid + w * 128] = xg[tid + w * 128];
    }
    __syncthreads();

    // ---- GEMM: acc[c pairs] for this thread's f-column (f row = tid) ----
    unsigned long long acc[8];
    #pragma unroll
    for (int q = 0; q < 8; q++) acc[q] = 0ull;

    const float4* fptr =
        (const float4*)(f_feats + (size_t)n * (NF * ND) + (size_t)tid * ND);

    #pragma unroll 1
    for (int kc = 0; kc < 32; kc++) {          // 32 chunks x 16 d
        float fr[16];
        #pragma unroll
        for (int t = 0; t < 4; t++)
            *(float4*)(fr + 4 * t) = fptr[kc * 4 + t];   // own row: 1 L1 line

        #pragma unroll
        for (int d = 0; d < 16; d++) {
            unsigned long long bb;
            asm("mov.b64 %0, {%1, %1};" : "=l"(bb) : "f"(fr[d]));
            const ulonglong2* xrow =
                (const ulonglong2*)(xs + (kc * 16 + d) * NC);
            ulonglong2 x0 = xrow[0];
            ulonglong2 x1 = xrow[1];
            ulonglong2 x2 = xrow[2];
            ulonglong2 x3 = xrow[3];
            fma2(acc[0], x0.x, bb); fma2(acc[1], x0.y, bb);
            fma2(acc[2], x1.x, bb); fma2(acc[3], x1.y, bb);
            fma2(acc[4], x2.x, bb); fma2(acc[5], x2.y, bb);
            fma2(acc[6], x3.x, bb); fma2(acc[7], x3.y, bb);
        }
    }
    __syncthreads();   // xs no longer needed; smem becomes Dm/mask

    const float fnrm = g_fnorm[n * NF + tid];

    // ---- init DP row 0 and zero the mask ----
    Dm[tid + 1] = NEG_INF;
    if (tid == 0) Dm[0] = 0.0f;
    {
        float4 z = make_float4(0.f, 0.f, 0.f, 0.f);
        float4* m4 = (float4*)mask;
        #pragma unroll
        for (int w = 0; w < 4; w++) m4[tid + w * 128] = z;
    }
    __syncthreads();

    // ---- DP rows: D[i,j] = Ccum[j] + cummax_k<=j(A[k] - Ccum[k-1]) ----
    for (int i = 1; i <= NC; i++) {
        const int c = i - 1;
        unsigned long long av = acc[c >> 1];
        float s = (c & 1) ? __uint_as_float((unsigned)(av >> 32))
                          : __uint_as_float((unsigned)(av & 0xffffffffu));
        if (tid <= c) s = s / fnrm;   // tri region uses normalized similarity

        const float* Pv = Dm + (size_t)(i - 1) * 129;
        float A = fmaxf(Pv[tid], Pv[tid + 1]);   // max(diag, up)

        // inclusive block cumsum of s
        float cs = s;
        #pragma unroll
        for (int o = 1; o < 32; o <<= 1) {
            float t = __shfl_up_sync(0xffffffffu, cs, o);
            if (lane >= o) cs += t;
        }
        if (lane == 31) wrs[wid] = cs;
        __syncthreads();
        float pre = 0.0f;
        if (wid > 0) pre += wrs[0];
        if (wid > 1) pre += wrs[1];
        if (wid > 2) pre += wrs[2];
        float Ccum = pre + cs;
        // Cm1 = Ccum of thread tid-1, reconstructed bit-exactly:
        float csp = __shfl_up_sync(0xffffffffu, cs, 1);
        float Cm1 = (lane == 0) ? pre : (pre + csp);   // tid==0 -> pre==0
        float T = A - Cm1;

        // inclusive block cummax of T (exact)
        float mx = T;
        #pragma unroll
        for (int o = 1; o < 32; o <<= 1) {
            float t = __shfl_up_sync(0xffffffffu, mx, o);
            if (lane >= o) mx = fmaxf(mx, t);
        }
        if (lane == 31) wrm[wid] = mx;
        __syncthreads();
        if (wid > 0) mx = fmaxf(mx, wrm[0]);
        if (wid > 1) mx = fmaxf(mx, wrm[1]);
        if (wid > 2) mx = fmaxf(mx, wrm[2]);

        Dm[i * 129 + tid + 1] = Ccum + mx;
        if (tid == 0) Dm[i * 129] = NEG_INF;
        __syncthreads();
    }

    // ---- backtrack (argmax first-max: up > left > diag), serial thread ----
    if (tid == 0) {
        int i = NC, j = NF;
        #pragma unroll 1
        for (int step = 0; step < NC + NF && (i > 0 && j > 0); step++) {
            mask[(i - 1) * NF + (j - 1)] = 1.0f;
            float up = Dm[(i - 1) * 129 + j];
            float lf = Dm[i * 129 + (j - 1)];
            float dg = Dm[(i - 1) * 129 + (j - 1)];
            int mv;
            if (up >= lf && up >= dg) mv = 0;
            else if (lf >= dg)        mv = 1;
            else                      mv = 2;
            if (mv != 1) i--;
            if (mv != 0) j--;
        }
    }
    __syncthreads();

    // ---- store mask [16][128] coalesced ----
    {
        float4*       og  = (float4*)(out + (size_t)(m * NB + n) * (NC * NF));
        const float4* ms4 = (const float4*)mask;
        #pragma unroll
        for (int w = 0; w < 4; w++) og[tid + w * 128] = ms4[tid + w * 128];
    }
}

// ---------------------------------------------------------------------------
extern "C" void kernel_launch(void* const* d_in, const int* in_sizes, int n_in,
                              void* d_out, int out_size)
{
    const float* c_feats = (const float*)d_in[0];
    const float* f_feats = (const float*)d_in[1];
    float* out = (float*)d_out;

    prep_kernel<<<NB * NC + NB * NF, 128>>>(c_feats, f_feats);
    dtw_kernel<<<NB * NB, 128>>>(f_feats, out);
}

// round 7
// speedup vs baseline: 1.4619x; 1.4619x over previous
#include <cuda_runtime.h>
#include <cstdint>

#define NB 128   // batch
#define NC 16    // c rows
#define NF 128   // f cols
#define ND 512   // feature dim
#define NEG_INF __int_as_float(0xff800000)

// Scratch (no cudaMalloc allowed): xn stored transposed per m: [m][d][c]
__device__ float g_xnT[NB * ND * NC];     // 4 MB
__device__ float g_fnorm[NB * NF];        // 64 KB

// ---------------------------------------------------------------------------
// Kernel 1: normalize c_feats (store d-major transposed) + f row norms
// ---------------------------------------------------------------------------
__global__ void __launch_bounds__(128) prep_kernel(
    const float* __restrict__ c_feats, const float* __restrict__ f_feats)
{
    const int b   = blockIdx.x;
    const int tid = threadIdx.x;
    const bool is_c = (b < NB * NC);
    const float* row = is_c ? (c_feats + (size_t)b * ND)
                            : (f_feats + (size_t)(b - NB * NC) * ND);
    float4 x = ((const float4*)row)[tid];   // 128 threads * 4 = 512
    float ss = x.x * x.x + x.y * x.y + x.z * x.z + x.w * x.w;
    #pragma unroll
    for (int o = 16; o; o >>= 1) ss += __shfl_xor_sync(0xffffffffu, ss, o);
    __shared__ float wr[4];
    if ((tid & 31) == 0) wr[tid >> 5] = ss;
    __syncthreads();
    float nrm = sqrtf(wr[0] + wr[1] + wr[2] + wr[3]);

    if (is_c) {
        int m = b >> 4, c = b & 15;
        float* dst = g_xnT + (size_t)m * (ND * NC) + c;
        int d0 = tid * 4;
        dst[(size_t)(d0 + 0) * NC] = x.x / nrm;
        dst[(size_t)(d0 + 1) * NC] = x.y / nrm;
        dst[(size_t)(d0 + 2) * NC] = x.z / nrm;
        dst[(size_t)(d0 + 3) * NC] = x.w / nrm;
    } else {
        if (tid == 0) g_fnorm[b - NB * NC] = nrm;
    }
}

// ---------------------------------------------------------------------------
// Kernel 2: per-pair register-tiled GEMM (4c x 4f per thread) + DTW.
// One CTA per (m,n) pair, 128 threads: cg = tid&3 (c block), fg = tid>>2 (f block).
//
// SMEM union (floats), 6432 total (25.7 KB):
//   GEMM phase : xsC [0, 512)        x chunk [32 k][16 c]
//                fsC [512, 5120)     f chunk [128 f][36]  (k-contiguous, pad 36)
//   DP phase   : Sbuf[0, 2176)       S [128 f][17]  (pad 17, conflict-free)
//                Dm  [2176, 4369)    DP table [17][129]
//                wrs [4376,4380) wrm [4380,4384)
//                mask[4384, 6432)    [16][128]
// ---------------------------------------------------------------------------
#define FS_STRIDE 36
#define OFF_FS   512
#define OFF_DM   2176
#define OFF_WRS  4376
#define OFF_WRM  4380
#define OFF_MASK 4384
#define SMEM_FLOATS 6432

__device__ __forceinline__ void fma2(unsigned long long& d,
                                     unsigned long long a,
                                     unsigned long long b) {
    asm("fma.rn.f32x2 %0, %1, %2, %0;" : "+l"(d) : "l"(a), "l"(b));
}

__global__ void __launch_bounds__(128, 8) dtw_kernel(
    const float* __restrict__ f_feats, float* __restrict__ out)
{
    __shared__ float smem[SMEM_FLOATS];
    float* xsC  = smem;
    float* fsC  = smem + OFF_FS;
    float* Sbuf = smem;
    float* Dm   = smem + OFF_DM;
    float* wrs  = smem + OFF_WRS;
    float* wrm  = smem + OFF_WRM;
    float* mask = smem + OFF_MASK;

    const int pair = blockIdx.x;
    const int m = pair & 127;      // m fastest -> concurrent CTAs share f[n]
    const int n = pair >> 7;
    const int tid  = threadIdx.x;
    const int lane = tid & 31;
    const int wid  = tid >> 5;
    const int cg   = tid & 3;      // c block: rows 4*cg .. 4*cg+3
    const int fg   = tid >> 2;     // f block: cols 4*fg .. 4*fg+3

    // acc[p][j]: packed pair (S[4cg+2p][4fg+j], S[4cg+2p+1][4fg+j])
    unsigned long long acc[2][4];
    #pragma unroll
    for (int p = 0; p < 2; p++)
        #pragma unroll
        for (int j = 0; j < 4; j++) acc[p][j] = 0ull;

    const float4* xg4   = (const float4*)(g_xnT + (size_t)m * (ND * NC));
    const float*  fbase = f_feats + (size_t)n * (NF * ND);

    const int ld_row = tid >> 3;       // f staging: 4 rows per warp slice
    const int ld_c4  = tid & 7;        // 8 float4 chunks per row

    #pragma unroll 1
    for (int chunk = 0; chunk < 16; chunk++) {   // 16 chunks x 32 k
        __syncthreads();
        // stage x chunk [32][16]: contiguous copy (coalesced, conflict-free)
        ((float4*)xsC)[tid] = xg4[chunk * 128 + tid];
        // stage f chunk [128][32] -> fsC[row][36] (coalesced LDG, vector STS)
        #pragma unroll
        for (int it = 0; it < 8; it++) {
            int row = ld_row + it * 16;
            float4 v = *(const float4*)(fbase + (size_t)row * ND
                                        + chunk * 32 + ld_c4 * 4);
            *(float4*)(fsC + row * FS_STRIDE + ld_c4 * 4) = v;
        }
        __syncthreads();

        #pragma unroll
        for (int k4 = 0; k4 < 8; k4++) {         // 8 groups of 4 k
            float fv[4][4];
            #pragma unroll
            for (int j = 0; j < 4; j++)
                *(float4*)fv[j] =
                    *(const float4*)(fsC + (fg * 4 + j) * FS_STRIDE + k4 * 4);
            #pragma unroll
            for (int kk = 0; kk < 4; kk++) {
                ulonglong2 xv =
                    *(const ulonglong2*)(xsC + (k4 * 4 + kk) * NC + cg * 4);
                #pragma unroll
                for (int j = 0; j < 4; j++) {
                    unsigned long long bb;
                    asm("mov.b64 %0, {%1, %1};" : "=l"(bb) : "f"(fv[j][kk]));
                    fma2(acc[0][j], xv.x, bb);
                    fma2(acc[1][j], xv.y, bb);
                }
            }
        }
    }
    __syncthreads();   // GEMM smem dead; becomes Sbuf/Dm/mask

    // ---- spill S to SMEM: Sbuf[f][c], stride 17 ----
    #pragma unroll
    for (int p = 0; p < 2; p++)
        #pragma unroll
        for (int j = 0; j < 4; j++) {
            unsigned long long v = acc[p][j];
            float s0 = __uint_as_float((unsigned)(v & 0xffffffffu));
            float s1 = __uint_as_float((unsigned)(v >> 32));
            int f = fg * 4 + j, c = cg * 4 + 2 * p;
            Sbuf[f * 17 + c]     = s0;
            Sbuf[f * 17 + c + 1] = s1;
        }

    const float fnrm = g_fnorm[n * NF + tid];

    // ---- init DP row 0 and zero the mask ----
    Dm[tid + 1] = NEG_INF;
    if (tid == 0) Dm[0] = 0.0f;
    {
        float4 z = make_float4(0.f, 0.f, 0.f, 0.f);
        float4* m4 = (float4*)mask;
        #pragma unroll
        for (int w = 0; w < 4; w++) m4[tid + w * 128] = z;
    }
    __syncthreads();

    // ---- DP rows: D[i,j] = Ccum[j] + cummax_k<=j(A[k] - Ccum[k-1]) ----
    for (int i = 1; i <= NC; i++) {
        const int c = i - 1;
        float s = Sbuf[tid * 17 + c];
        if (tid <= c) s = s / fnrm;   // tri region uses normalized similarity

        const float* Pv = Dm + (size_t)(i - 1) * 129;
        float A = fmaxf(Pv[tid], Pv[tid + 1]);   // max(diag, up)

        // inclusive block cumsum of s
        float cs = s;
        #pragma unroll
        for (int o = 1; o < 32; o <<= 1) {
            float t = __shfl_up_sync(0xffffffffu, cs, o);
            if (lane >= o) cs += t;
        }
        if (lane == 31) wrs[wid] = cs;
        __syncthreads();
        float pre = 0.0f;
        if (wid > 0) pre += wrs[0];
        if (wid > 1) pre += wrs[1];
        if (wid > 2) pre += wrs[2];
        float Ccum = pre + cs;
        // Cm1 = Ccum of thread tid-1, reconstructed bit-exactly:
        float csp = __shfl_up_sync(0xffffffffu, cs, 1);
        float Cm1 = (lane == 0) ? pre : (pre + csp);   // tid==0 -> pre==0
        float T = A - Cm1;

        // inclusive block cummax of T (exact)
        float mx = T;
        #pragma unroll
        for (int o = 1; o < 32; o <<= 1) {
            float t = __shfl_up_sync(0xffffffffu, mx, o);
            if (lane >= o) mx = fmaxf(mx, t);
        }
        if (lane == 31) wrm[wid] = mx;
        __syncthreads();
        if (wid > 0) mx = fmaxf(mx, wrm[0]);
        if (wid > 1) mx = fmaxf(mx, wrm[1]);
        if (wid > 2) mx = fmaxf(mx, wrm[2]);

        Dm[i * 129 + tid + 1] = Ccum + mx;
        if (tid == 0) Dm[i * 129] = NEG_INF;
        __syncthreads();
    }

    // ---- backtrack (argmax first-max: up > left > diag), serial thread ----
    if (tid == 0) {
        int i = NC, j = NF;
        #pragma unroll 1
        for (int step = 0; step < NC + NF && (i > 0 && j > 0); step++) {
            mask[(i - 1) * NF + (j - 1)] = 1.0f;
            float up = Dm[(i - 1) * 129 + j];
            float lf = Dm[i * 129 + (j - 1)];
            float dg = Dm[(i - 1) * 129 + (j - 1)];
            int mv;
            if (up >= lf && up >= dg) mv = 0;
            else if (lf >= dg)        mv = 1;
            else                      mv = 2;
            if (mv != 1) i--;
            if (mv != 0) j--;
        }
    }
    __syncthreads();

    // ---- store mask [16][128] coalesced ----
    {
        float4*       og  = (float4*)(out + (size_t)(m * NB + n) * (NC * NF));
        const float4* ms4 = (const float4*)mask;
        #pragma unroll
        for (int w = 0; w < 4; w++) og[tid + w * 128] = ms4[tid + w * 128];
    }
}

// ---------------------------------------------------------------------------
extern "C" void kernel_launch(void* const* d_in, const int* in_sizes, int n_in,
                              void* d_out, int out_size)
{
    const float* c_feats = (const float*)d_in[0];
    const float* f_feats = (const float*)d_in[1];
    float* out = (float*)d_out;

    prep_kernel<<<NB * NC + NB * NF, 128>>>(c_feats, f_feats);
    dtw_kernel<<<NB * NB, 128>>>(f_feats, out);
}

// round 10
// speedup vs baseline: 1.6079x; 1.0998x over previous
#include <cuda_runtime.h>
#include <cstdint>

#define NB 128   // batch
#define NC 16    // c rows
#define NF 128   // f cols
#define ND 512   // feature dim
#define NEG_INF __int_as_float(0xff800000)

// Scratch (no cudaMalloc allowed)
__device__ float g_xnT[NB * ND * NC];     // 4 MB  : xn transposed [m][d][c]
__device__ float g_fT [NB * ND * NF];     // 32 MB : f transposed  [n][d][f]
__device__ float g_fnorm[NB * NF];        // 64 KB

// ---------------------------------------------------------------------------
// Kernel 1: normalize c_feats (store d-major transposed) + f row norms
// ---------------------------------------------------------------------------
__global__ void __launch_bounds__(128) prep_kernel(
    const float* __restrict__ c_feats, const float* __restrict__ f_feats)
{
    const int b   = blockIdx.x;
    const int tid = threadIdx.x;
    const bool is_c = (b < NB * NC);
    const float* row = is_c ? (c_feats + (size_t)b * ND)
                            : (f_feats + (size_t)(b - NB * NC) * ND);
    float4 x = ((const float4*)row)[tid];   // 128 threads * 4 = 512
    float ss = x.x * x.x + x.y * x.y + x.z * x.z + x.w * x.w;
    #pragma unroll
    for (int o = 16; o; o >>= 1) ss += __shfl_xor_sync(0xffffffffu, ss, o);
    __shared__ float wr[4];
    if ((tid & 31) == 0) wr[tid >> 5] = ss;
    __syncthreads();
    float nrm = sqrtf(wr[0] + wr[1] + wr[2] + wr[3]);

    if (is_c) {
        int m = b >> 4, c = b & 15;
        float* dst = g_xnT + (size_t)m * (ND * NC) + c;
        int d0 = tid * 4;
        dst[(size_t)(d0 + 0) * NC] = x.x / nrm;
        dst[(size_t)(d0 + 1) * NC] = x.y / nrm;
        dst[(size_t)(d0 + 2) * NC] = x.z / nrm;
        dst[(size_t)(d0 + 3) * NC] = x.w / nrm;
    } else {
        if (tid == 0) g_fnorm[b - NB * NC] = nrm;
    }
}

// ---------------------------------------------------------------------------
// Kernel 1b: transpose f_feats [n][f][d] -> g_fT [n][d][f]
// grid (4 f-tiles, 16 d-tiles, 128 n), block (32, 8)
// ---------------------------------------------------------------------------
__global__ void __launch_bounds__(256) transpose_f_kernel(
    const float* __restrict__ f_feats)
{
    __shared__ float t[32][33];
    const int ft = blockIdx.x, dt = blockIdx.y, n = blockIdx.z;
    const int x = threadIdx.x, y = threadIdx.y;

    const float* src = f_feats + ((size_t)n * NF + ft * 32) * ND + dt * 32;
    #pragma unroll
    for (int r = 0; r < 32; r += 8)
        t[y + r][x] = src[(size_t)(y + r) * ND + x];
    __syncthreads();
    float* dst = g_fT + (size_t)n * (ND * NF) + (size_t)(dt * 32) * NF + ft * 32;
    #pragma unroll
    for (int r = 0; r < 32; r += 8)
        dst[(size_t)(y + r) * NF + x] = t[x][y + r];
}

// ---------------------------------------------------------------------------
// Kernel 2: per-pair register-tiled GEMM (4c x 4f per thread) + DTW.
// One CTA per (m,n) pair, 128 threads: cg = tid&3, fg = tid>>2.
// f read DIRECTLY from g_fT (k-major): per k one LDG.128 hitting a single
// 128B line per warp (8 distinct float4, 4-lane broadcast). Only x staged
// in SMEM (double-buffered, 1 sync/chunk).
//
// SMEM union (floats), 6432 total (25.7 KB):
//   GEMM phase : xs  [0, 1024)       x chunks, 2 x [32 k][16 c]
//   DP phase   : Sbuf[0, 2176)       S [128 f][17]
//                Dm  [2176, 4369)    DP table [17][129]
//                wrs [4376,4380) wrm [4380,4384)
//                mask[4384, 6432)    [16][128]
// ---------------------------------------------------------------------------
#define OFF_DM   2176
#define OFF_WRS  4376
#define OFF_WRM  4380
#define OFF_MASK 4384
#define SMEM_FLOATS 6432

__device__ __forceinline__ void fma2(unsigned long long& d,
                                     unsigned long long a,
                                     unsigned long long b) {
    asm("fma.rn.f32x2 %0, %1, %2, %0;" : "+l"(d) : "l"(a), "l"(b));
}

__global__ void __launch_bounds__(128, 8) dtw_kernel(float* __restrict__ out)
{
    __shared__ float smem[SMEM_FLOATS];
    float* xs   = smem;            // [2][512]
    float* Sbuf = smem;
    float* Dm   = smem + OFF_DM;
    float* wrs  = smem + OFF_WRS;
    float* wrm  = smem + OFF_WRM;
    float* mask = smem + OFF_MASK;

    const int pair = blockIdx.x;
    const int m = pair & 127;      // m fastest -> concurrent CTAs share f[n]
    const int n = pair >> 7;
    const int tid  = threadIdx.x;
    const int lane = tid & 31;
    const int wid  = tid >> 5;
    const int cg   = tid & 3;      // c block: rows 4*cg .. 4*cg+3
    const int fg   = tid >> 2;     // f block: cols 4*fg .. 4*fg+3

    // acc[p][j]: packed pair (S[4cg+2p][4fg+j], S[4cg+2p+1][4fg+j])
    unsigned long long acc[2][4];
    #pragma unroll
    for (int p = 0; p < 2; p++)
        #pragma unroll
        for (int j = 0; j < 4; j++) acc[p][j] = 0ull;

    const float4* xg4 = (const float4*)(g_xnT + (size_t)m * (ND * NC));
    const float*  fT  = g_fT + (size_t)n * (ND * NF);

    // prime x buffer 0
    ((float4*)xs)[tid] = xg4[tid];
    __syncthreads();

    #pragma unroll 1
    for (int chunk = 0; chunk < 16; chunk++) {   // 16 chunks x 32 k
        const float* cur = xs + (chunk & 1) * 512;
        if (chunk < 15)
            ((float4*)(xs + ((chunk + 1) & 1) * 512))[tid] =
                xg4[(chunk + 1) * 128 + tid];

        const float* fk = fT + (size_t)chunk * 32 * NF + fg * 4;
        #pragma unroll 4
        for (int k = 0; k < 32; k++) {
            float4 fv = *(const float4*)(fk + (size_t)k * NF);   // 1 line/warp
            ulonglong2 xv = *(const ulonglong2*)(cur + k * NC + cg * 4);
            unsigned long long b0, b1, b2, b3;
            asm("mov.b64 %0, {%1, %1};" : "=l"(b0) : "f"(fv.x));
            asm("mov.b64 %0, {%1, %1};" : "=l"(b1) : "f"(fv.y));
            asm("mov.b64 %0, {%1, %1};" : "=l"(b2) : "f"(fv.z));
            asm("mov.b64 %0, {%1, %1};" : "=l"(b3) : "f"(fv.w));
            fma2(acc[0][0], xv.x, b0); fma2(acc[1][0], xv.y, b0);
            fma2(acc[0][1], xv.x, b1); fma2(acc[1][1], xv.y, b1);
            fma2(acc[0][2], xv.x, b2); fma2(acc[1][2], xv.y, b2);
            fma2(acc[0][3], xv.x, b3); fma2(acc[1][3], xv.y, b3);
        }
        __syncthreads();   // next buffer ready + cur free for overwrite
    }

    // ---- spill S to SMEM: Sbuf[f][c], stride 17 ----
    #pragma unroll
    for (int p = 0; p < 2; p++)
        #pragma unroll
        for (int j = 0; j < 4; j++) {
            unsigned long long v = acc[p][j];
            float s0 = __uint_as_float((unsigned)(v & 0xffffffffu));
            float s1 = __uint_as_float((unsigned)(v >> 32));
            int f = fg * 4 + j, c = cg * 4 + 2 * p;
            Sbuf[f * 17 + c]     = s0;
            Sbuf[f * 17 + c + 1] = s1;
        }

    const float fnrm = g_fnorm[n * NF + tid];

    // ---- init DP row 0 and zero the mask ----
    Dm[tid + 1] = NEG_INF;
    if (tid == 0) Dm[0] = 0.0f;
    {
        float4 z = make_float4(0.f, 0.f, 0.f, 0.f);
        float4* m4 = (float4*)mask;
        #pragma unroll
        for (int w = 0; w < 4; w++) m4[tid + w * 128] = z;
    }
    __syncthreads();

    // ---- DP rows: D[i,j] = Ccum[j] + cummax_k<=j(A[k] - Ccum[k-1]) ----
    for (int i = 1; i <= NC; i++) {
        const int c = i - 1;
        float s = Sbuf[tid * 17 + c];
        if (tid <= c) s = s / fnrm;   // tri region uses normalized similarity

        const float* Pv = Dm + (size_t)(i - 1) * 129;
        float A = fmaxf(Pv[tid], Pv[tid + 1]);   // max(diag, up)

        // inclusive block cumsum of s
        float cs = s;
        #pragma unroll
        for (int o = 1; o < 32; o <<= 1) {
            float t = __shfl_up_sync(0xffffffffu, cs, o);
            if (lane >= o) cs += t;
        }
        if (lane == 31) wrs[wid] = cs;
        __syncthreads();
        float pre = 0.0f;
        if (wid > 0) pre += wrs[0];
        if (wid > 1) pre += wrs[1];
        if (wid > 2) pre += wrs[2];
        float Ccum = pre + cs;
        // Cm1 = Ccum of thread tid-1, reconstructed bit-exactly:
        float csp = __shfl_up_sync(0xffffffffu, cs, 1);
        float Cm1 = (lane == 0) ? pre : (pre + csp);   // tid==0 -> pre==0
        float T = A - Cm1;

        // inclusive block cummax of T (exact)
        float mx = T;
        #pragma unroll
        for (int o = 1; o < 32; o <<= 1) {
            float t = __shfl_up_sync(0xffffffffu, mx, o);
            if (lane >= o) mx = fmaxf(mx, t);
        }
        if (lane == 31) wrm[wid] = mx;
        __syncthreads();
        if (wid > 0) mx = fmaxf(mx, wrm[0]);
        if (wid > 1) mx = fmaxf(mx, wrm[1]);
        if (wid > 2) mx = fmaxf(mx, wrm[2]);

        Dm[i * 129 + tid + 1] = Ccum + mx;
        if (tid == 0) Dm[i * 129] = NEG_INF;
        __syncthreads();
    }

    // ---- backtrack (argmax first-max: up > left > diag), serial thread ----
    if (tid == 0) {
        int i = NC, j = NF;
        #pragma unroll 1
        for (int step = 0; step < NC + NF && (i > 0 && j > 0); step++) {
            mask[(i - 1) * NF + (j - 1)] = 1.0f;
            float up = Dm[(i - 1) * 129 + j];
            float lf = Dm[i * 129 + (j - 1)];
            float dg = Dm[(i - 1) * 129 + (j - 1)];
            int mv;
            if (up >= lf && up >= dg) mv = 0;
            else if (lf >= dg)        mv = 1;
            else                      mv = 2;
            if (mv != 1) i--;
            if (mv != 0) j--;
        }
    }
    __syncthreads();

    // ---- store mask [16][128] coalesced ----
    {
        float4*       og  = (float4*)(out + (size_t)(m * NB + n) * (NC * NF));
        const float4* ms4 = (const float4*)mask;
        #pragma unroll
        for (int w = 0; w < 4; w++) og[tid + w * 128] = ms4[tid + w * 128];
    }
}

// ---------------------------------------------------------------------------
extern "C" void kernel_launch(void* const* d_in, const int* in_sizes, int n_in,
                              void* d_out, int out_size)
{
    const float* c_feats = (const float*)d_in[0];
    const float* f_feats = (const float*)d_in[1];
    float* out = (float*)d_out;

    prep_kernel<<<NB * NC + NB * NF, 128>>>(c_feats, f_feats);
    transpose_f_kernel<<<dim3(4, 16, NB), dim3(32, 8)>>>(f_feats);
    dtw_kernel<<<NB * NB, 128>>>(out);
}